// round 10
// baseline (speedup 1.0000x reference)
#include <cuda_runtime.h>

// BilinearInterpolation: B=16, H=W=512, C=16 fp32.
// R10: identical structure to R9 (16 output rows/block, rolling 2-row cache of
// horizontal interpolants, thread-per-quad, f32x2 math), but the streaming
// store uses the __stcs() intrinsic instead of asm volatile+memory clobber.
// The R9 asm barrier serialized every iteration (load->blend->store->load);
// with __restrict__ + intrinsic store, ptxas can hoist next-row gathers above
// stores and software-pipeline the unrolled loop (restores MLP).

#define BB 16
#define HH 512
#define WW 512
#define ROWS 16

typedef unsigned long long u64;

__device__ __forceinline__ u64 pk2(float v) {
    u64 r; asm("mov.b64 %0, {%1, %1};" : "=l"(r) : "f"(v)); return r;
}
__device__ __forceinline__ u64 mul2(u64 a, u64 b) {
    u64 r; asm("mul.rn.f32x2 %0, %1, %2;" : "=l"(r) : "l"(a), "l"(b)); return r;
}
__device__ __forceinline__ u64 fma2(u64 a, u64 b, u64 c) {
    u64 r; asm("fma.rn.f32x2 %0, %1, %2, %3;" : "=l"(r) : "l"(a), "l"(b), "l"(c)); return r;
}

struct H2 { u64 x, y; };   // horizontal interpolant of one input row (4 floats)

__device__ __forceinline__ H2 hload(const ulonglong2* __restrict__ row,
                                    int c0, int c1, u64 dx0, u64 dx1)
{
    const ulonglong2 p0 = __ldg(row + c0);
    const ulonglong2 p1 = __ldg(row + c1);
    H2 h;
    h.x = fma2(dx1, p0.x, mul2(dx0, p1.x));
    h.y = fma2(dx1, p0.y, mul2(dx0, p1.y));
    return h;
}

__global__ void __launch_bounds__(256)
bilinear_16row_kernel(const ulonglong2* __restrict__ X,
                      const float* __restrict__ scale,
                      const float* __restrict__ translate,
                      ulonglong2* __restrict__ out)
{
    const int t   = threadIdx.x;
    const int b   = blockIdx.z;            // uniform
    const int oy0 = blockIdx.y * ROWS;     // uniform

    // ---- uniform batch params ----
    const float s  = __ldg(&scale[b]);
    const float tx = __ldg(&translate[2 * b]);
    const float ty = __ldg(&translate[2 * b + 1]);

    // ---- per-thread x-side math (shared by all ROWS outputs) ----
    const int q  = t & 3;
    const int ox = (blockIdx.x << 6) + (t >> 2);
    const float xc = fmaf((float)ox, 2.0f / 511.0f, -1.0f);
    const float x  = 0.5f * (fmaf(s, xc, tx) + 1.0f) * (float)WW;
    int x0 = (int)x;            // trunc toward zero (matches astype(int32))
    int x1 = x0 + 1;
    x0 = min(max(x0, 0), WW - 1);
    x1 = min(max(x1, 0), WW - 1);
    const u64 dx1 = pk2((float)x1 - x);
    const u64 dx0 = pk2(x - (float)x0);

    const int c0 = (x0 << 2) + q;
    const int c1 = (x1 << 2) + q;

    const ulonglong2* __restrict__ Xb = X + b * (HH * WW * 4);
    ulonglong2* __restrict__ O = out + ((b * HH + oy0) << 11) + (blockIdx.x << 8) + t;

    // rolling 2-row cache of horizontal interpolants
    int cur0 = -9, cur1 = -9;
    H2 h0, h1;

    #pragma unroll
    for (int r = 0; r < ROWS; ++r) {
        // ---- uniform y-side math for this output row ----
        const float yc = fmaf((float)(oy0 + r), 2.0f / 511.0f, -1.0f);
        const float y  = 0.5f * (fmaf(s, yc, ty) + 1.0f) * (float)HH;
        int y0 = (int)y;
        int y1 = y0 + 1;
        y0 = min(max(y0, 0), HH - 1);
        y1 = min(max(y1, 0), HH - 1);
        const u64 dy1 = pk2((float)y1 - y);
        const u64 dy0 = pk2(y - (float)y0);

        // ---- uniform row-cache update ----
        if (y0 == cur0 && y1 == cur1) {
            // full reuse: 0 loads
        } else if (y0 == cur1) {
            // shift: reuse hi as lo, load new hi (covers clamp-straddle too)
            h0 = h1;
            h1 = hload(Xb + (y1 << 11), c0, c1, dx0, dx1);
            cur0 = y0; cur1 = y1;
        } else {
            h0 = hload(Xb + (y0 << 11), c0, c1, dx0, dx1);
            h1 = hload(Xb + (y1 << 11), c0, c1, dx0, dx1);
            cur0 = y0; cur1 = y1;
        }

        // ---- vertical blend + streaming store (no compiler barrier) ----
        ulonglong2 o;
        o.x = fma2(dy1, h0.x, mul2(dy0, h1.x));
        o.y = fma2(dy1, h0.y, mul2(dy0, h1.y));
        __stcs(O + (r << 11), o);
    }
}

extern "C" void kernel_launch(void* const* d_in, const int* in_sizes, int n_in,
                              void* d_out, int out_size)
{
    const float* X         = (const float*)d_in[0];
    const float* scale     = (const float*)d_in[1];
    const float* translate = (const float*)d_in[2];

    dim3 grid(WW / 64, HH / ROWS, BB);   // (8, 32, 16) = 4096 blocks
    bilinear_16row_kernel<<<grid, 256>>>((const ulonglong2*)X, scale, translate,
                                         (ulonglong2*)d_out);
}

// round 11
// speedup vs baseline: 1.0013x; 1.0013x over previous
#include <cuda_runtime.h>

// BilinearInterpolation: B=16, H=W=512, C=16 fp32.
// R11: TWO independent row-chains per thread (8 rows each). Loop body issues
// BOTH chains' row-cache loads before either chain's blend consumes them, so
// with in-order issue both chains' gathers are in flight concurrently
// (per-warp MLP ~2x vs R10). Each chain is R9/R10's proven rolling cache of
// horizontal interpolants with uniform reuse/shift/reload branches.

#define BB 16
#define HH 512
#define WW 512
#define RPC 8     // rows per chain
#define ROWS 16   // rows per block (2 chains)

typedef unsigned long long u64;

__device__ __forceinline__ u64 pk2(float v) {
    u64 r; asm("mov.b64 %0, {%1, %1};" : "=l"(r) : "f"(v)); return r;
}
__device__ __forceinline__ u64 mul2(u64 a, u64 b) {
    u64 r; asm("mul.rn.f32x2 %0, %1, %2;" : "=l"(r) : "l"(a), "l"(b)); return r;
}
__device__ __forceinline__ u64 fma2(u64 a, u64 b, u64 c) {
    u64 r; asm("fma.rn.f32x2 %0, %1, %2, %3;" : "=l"(r) : "l"(a), "l"(b), "l"(c)); return r;
}

struct H2 { u64 x, y; };   // horizontal interpolant of one input row (4 floats)

__device__ __forceinline__ H2 hload(const ulonglong2* __restrict__ row,
                                    int c0, int c1, u64 dx0, u64 dx1)
{
    const ulonglong2 p0 = __ldg(row + c0);
    const ulonglong2 p1 = __ldg(row + c1);
    H2 h;
    h.x = fma2(dx1, p0.x, mul2(dx0, p1.x));
    h.y = fma2(dx1, p0.y, mul2(dx0, p1.y));
    return h;
}

// Uniform y-side math for one output row: returns packed dy weights and rows.
struct YInfo { int y0, y1; u64 dy0, dy1; };

__device__ __forceinline__ YInfo ymath(int oy, float s, float ty)
{
    const float yc = fmaf((float)oy, 2.0f / 511.0f, -1.0f);
    const float y  = 0.5f * (fmaf(s, yc, ty) + 1.0f) * (float)HH;
    int y0 = (int)y;            // trunc toward zero (matches astype(int32))
    int y1 = y0 + 1;
    y0 = min(max(y0, 0), HH - 1);
    y1 = min(max(y1, 0), HH - 1);
    YInfo yi;
    yi.y0 = y0; yi.y1 = y1;
    yi.dy1 = pk2((float)y1 - y);
    yi.dy0 = pk2(y - (float)y0);
    return yi;
}

__global__ void __launch_bounds__(256)
bilinear_2chain_kernel(const ulonglong2* __restrict__ X,
                       const float* __restrict__ scale,
                       const float* __restrict__ translate,
                       ulonglong2* __restrict__ out)
{
    const int t   = threadIdx.x;
    const int b   = blockIdx.z;            // uniform
    const int oyA = blockIdx.y * ROWS;     // uniform, chain A rows [oyA, oyA+8)
    const int oyB = oyA + RPC;             // chain B rows [oyA+8, oyA+16)

    // ---- uniform batch params ----
    const float s  = __ldg(&scale[b]);
    const float tx = __ldg(&translate[2 * b]);
    const float ty = __ldg(&translate[2 * b + 1]);

    // ---- per-thread x-side math (shared by all outputs) ----
    const int q  = t & 3;
    const int ox = (blockIdx.x << 6) + (t >> 2);
    const float xc = fmaf((float)ox, 2.0f / 511.0f, -1.0f);
    const float x  = 0.5f * (fmaf(s, xc, tx) + 1.0f) * (float)WW;
    int x0 = (int)x;
    int x1 = x0 + 1;
    x0 = min(max(x0, 0), WW - 1);
    x1 = min(max(x1, 0), WW - 1);
    const u64 dx1 = pk2((float)x1 - x);
    const u64 dx0 = pk2(x - (float)x0);

    const int c0 = (x0 << 2) + q;
    const int c1 = (x1 << 2) + q;

    const ulonglong2* __restrict__ Xb = X + b * (HH * WW * 4);
    ulonglong2* __restrict__ OA = out + ((b * HH + oyA) << 11) + (blockIdx.x << 8) + t;
    ulonglong2* __restrict__ OB = OA + (RPC << 11);

    // two independent rolling caches
    int cA0 = -9, cA1 = -9, cB0 = -9, cB1 = -9;
    H2 a0, a1, b0, b1;

    #pragma unroll
    for (int r = 0; r < RPC; ++r) {
        const YInfo yA = ymath(oyA + r, s, ty);
        const YInfo yB = ymath(oyB + r, s, ty);

        // ---- issue chain A loads ----
        if (yA.y0 == cA0 && yA.y1 == cA1) {
        } else if (yA.y0 == cA1) {
            a0 = a1;
            a1 = hload(Xb + (yA.y1 << 11), c0, c1, dx0, dx1);
            cA0 = yA.y0; cA1 = yA.y1;
        } else {
            a0 = hload(Xb + (yA.y0 << 11), c0, c1, dx0, dx1);
            a1 = hload(Xb + (yA.y1 << 11), c0, c1, dx0, dx1);
            cA0 = yA.y0; cA1 = yA.y1;
        }

        // ---- issue chain B loads (overlap with A's in-flight loads) ----
        if (yB.y0 == cB0 && yB.y1 == cB1) {
        } else if (yB.y0 == cB1) {
            b0 = b1;
            b1 = hload(Xb + (yB.y1 << 11), c0, c1, dx0, dx1);
            cB0 = yB.y0; cB1 = yB.y1;
        } else {
            b0 = hload(Xb + (yB.y0 << 11), c0, c1, dx0, dx1);
            b1 = hload(Xb + (yB.y1 << 11), c0, c1, dx0, dx1);
            cB0 = yB.y0; cB1 = yB.y1;
        }

        // ---- blends + streaming stores ----
        ulonglong2 oA;
        oA.x = fma2(yA.dy1, a0.x, mul2(yA.dy0, a1.x));
        oA.y = fma2(yA.dy1, a0.y, mul2(yA.dy0, a1.y));
        __stcs(OA + (r << 11), oA);

        ulonglong2 oB;
        oB.x = fma2(yB.dy1, b0.x, mul2(yB.dy0, b1.x));
        oB.y = fma2(yB.dy1, b0.y, mul2(yB.dy0, b1.y));
        __stcs(OB + (r << 11), oB);
    }
}

extern "C" void kernel_launch(void* const* d_in, const int* in_sizes, int n_in,
                              void* d_out, int out_size)
{
    const float* X         = (const float*)d_in[0];
    const float* scale     = (const float*)d_in[1];
    const float* translate = (const float*)d_in[2];

    dim3 grid(WW / 64, HH / ROWS, BB);   // (8, 32, 16) = 4096 blocks
    bilinear_2chain_kernel<<<grid, 256>>>((const ulonglong2*)X, scale, translate,
                                          (ulonglong2*)d_out);
}

// round 12
// speedup vs baseline: 1.0071x; 1.0058x over previous
#include <cuda_runtime.h>

// BilinearInterpolation: B=16, H=W=512, C=16 fp32.
// R12: BRANCH-FREE row advance. s<1 => y0 advances by 0 or 1 per output row,
// so the rolling cache update is a register SELECT (h0 = adv ? h1 : h0) and
// h1 is reloaded unconditionally every row (L1 hit when redundant). The fully
// unrolled body has no runtime branches, letting ptxas software-pipeline
// LDGs across iterations (the branch structure was what pinned MLP~2 in
// R9-R11). 16 rows/block, thread-per-quad, f32x2 packed math, __stcs stores.

#define BB 16
#define HH 512
#define WW 512
#define ROWS 16

typedef unsigned long long u64;

__device__ __forceinline__ u64 pk2(float v) {
    u64 r; asm("mov.b64 %0, {%1, %1};" : "=l"(r) : "f"(v)); return r;
}
__device__ __forceinline__ u64 mul2(u64 a, u64 b) {
    u64 r; asm("mul.rn.f32x2 %0, %1, %2;" : "=l"(r) : "l"(a), "l"(b)); return r;
}
__device__ __forceinline__ u64 fma2(u64 a, u64 b, u64 c) {
    u64 r; asm("fma.rn.f32x2 %0, %1, %2, %3;" : "=l"(r) : "l"(a), "l"(b), "l"(c)); return r;
}

struct H2 { u64 x, y; };   // horizontal interpolant of one input row (4 floats)

__device__ __forceinline__ H2 hload(const ulonglong2* __restrict__ row,
                                    int c0, int c1, u64 dx0, u64 dx1)
{
    const ulonglong2 p0 = __ldg(row + c0);
    const ulonglong2 p1 = __ldg(row + c1);
    H2 h;
    h.x = fma2(dx1, p0.x, mul2(dx0, p1.x));
    h.y = fma2(dx1, p0.y, mul2(dx0, p1.y));
    return h;
}

__global__ void __launch_bounds__(256)
bilinear_bf_kernel(const ulonglong2* __restrict__ X,
                   const float* __restrict__ scale,
                   const float* __restrict__ translate,
                   ulonglong2* __restrict__ out)
{
    const int t   = threadIdx.x;
    const int b   = blockIdx.z;            // uniform
    const int oy0 = blockIdx.y * ROWS;     // uniform

    // ---- uniform batch params ----
    const float s  = __ldg(&scale[b]);
    const float tx = __ldg(&translate[2 * b]);
    const float ty = __ldg(&translate[2 * b + 1]);

    // ---- per-thread x-side math (shared by all ROWS outputs) ----
    const int q  = t & 3;
    const int ox = (blockIdx.x << 6) + (t >> 2);
    const float xc = fmaf((float)ox, 2.0f / 511.0f, -1.0f);
    const float x  = 0.5f * (fmaf(s, xc, tx) + 1.0f) * (float)WW;
    int x0 = (int)x;            // trunc toward zero (matches astype(int32))
    int x1 = x0 + 1;
    x0 = min(max(x0, 0), WW - 1);
    x1 = min(max(x1, 0), WW - 1);
    const u64 dx1 = pk2((float)x1 - x);
    const u64 dx0 = pk2(x - (float)x0);

    const int c0 = (x0 << 2) + q;
    const int c1 = (x1 << 2) + q;

    const ulonglong2* __restrict__ Xb = X + b * (HH * WW * 4);
    ulonglong2* __restrict__ O = out + ((b * HH + oy0) << 11) + (blockIdx.x << 8) + t;

    // ---- prologue: row 0 of this block ----
    float yc = fmaf((float)oy0, 2.0f / 511.0f, -1.0f);
    float y  = 0.5f * (fmaf(s, yc, ty) + 1.0f) * (float)HH;
    int y0 = (int)y;
    int y1 = y0 + 1;
    y0 = min(max(y0, 0), HH - 1);
    y1 = min(max(y1, 0), HH - 1);

    H2 h0 = hload(Xb + (y0 << 11), c0, c1, dx0, dx1);
    H2 h1 = hload(Xb + (y1 << 11), c0, c1, dx0, dx1);
    int cury0 = y0;

    {
        const u64 dy1 = pk2((float)y1 - y);
        const u64 dy0 = pk2(y - (float)y0);
        ulonglong2 o;
        o.x = fma2(dy1, h0.x, mul2(dy0, h1.x));
        o.y = fma2(dy1, h0.y, mul2(dy0, h1.y));
        __stcs(O, o);
    }

    // ---- branch-free main loop ----
    #pragma unroll
    for (int r = 1; r < ROWS; ++r) {
        yc = fmaf((float)(oy0 + r), 2.0f / 511.0f, -1.0f);
        y  = 0.5f * (fmaf(s, yc, ty) + 1.0f) * (float)HH;
        y0 = (int)y;
        y1 = y0 + 1;
        y0 = min(max(y0, 0), HH - 1);
        y1 = min(max(y1, 0), HH - 1);
        const u64 dy1 = pk2((float)y1 - y);
        const u64 dy0 = pk2(y - (float)y0);

        // register-select cache advance (s<1 => step 0 or 1; clamp-safe)
        const bool adv = (y0 != cury0);
        h0.x = adv ? h1.x : h0.x;
        h0.y = adv ? h1.y : h0.y;
        cury0 = y0;

        // unconditional reload of the high row (L1 hit when unchanged)
        h1 = hload(Xb + (y1 << 11), c0, c1, dx0, dx1);

        ulonglong2 o;
        o.x = fma2(dy1, h0.x, mul2(dy0, h1.x));
        o.y = fma2(dy1, h0.y, mul2(dy0, h1.y));
        __stcs(O + (r << 11), o);
    }
}

extern "C" void kernel_launch(void* const* d_in, const int* in_sizes, int n_in,
                              void* d_out, int out_size)
{
    const float* X         = (const float*)d_in[0];
    const float* scale     = (const float*)d_in[1];
    const float* translate = (const float*)d_in[2];

    dim3 grid(WW / 64, HH / ROWS, BB);   // (8, 32, 16) = 4096 blocks
    bilinear_bf_kernel<<<grid, 256>>>((const ulonglong2*)X, scale, translate,
                                      (ulonglong2*)d_out);
}

// round 13
// speedup vs baseline: 1.0123x; 1.0052x over previous
#include <cuda_runtime.h>

// BilinearInterpolation: B=16, H=W=512, C=16 fp32.
// R13: explicit depth-2 software pipeline. Raw pixel pairs for row y1(r) are
// loaded TWO iterations ahead and held in registers; horizontal interpolants
// are computed at consumption. Branch-free select-chain row advance (R12),
// 16 rows/block, thread-per-quad, f32x2 packed math, __stcs stores.

#define BB 16
#define HH 512
#define WW 512
#define ROWS 16

typedef unsigned long long u64;

__device__ __forceinline__ u64 pk2(float v) {
    u64 r; asm("mov.b64 %0, {%1, %1};" : "=l"(r) : "f"(v)); return r;
}
__device__ __forceinline__ u64 mul2(u64 a, u64 b) {
    u64 r; asm("mul.rn.f32x2 %0, %1, %2;" : "=l"(r) : "l"(a), "l"(b)); return r;
}
__device__ __forceinline__ u64 fma2(u64 a, u64 b, u64 c) {
    u64 r; asm("fma.rn.f32x2 %0, %1, %2, %3;" : "=l"(r) : "l"(a), "l"(b), "l"(c)); return r;
}

struct H2 { u64 x, y; };     // horizontal interpolant (4 floats)
struct P2 { ulonglong2 p0, p1; };   // raw pixel pair of one input row

__device__ __forceinline__ P2 rawload(const ulonglong2* __restrict__ row,
                                      int c0, int c1)
{
    P2 p;
    p.p0 = __ldg(row + c0);
    p.p1 = __ldg(row + c1);
    return p;
}

__device__ __forceinline__ H2 hcombine(P2 p, u64 dx0, u64 dx1)
{
    H2 h;
    h.x = fma2(dx1, p.p0.x, mul2(dx0, p.p1.x));
    h.y = fma2(dx1, p.p0.y, mul2(dx0, p.p1.y));
    return h;
}

// uniform y math for output row oy: clamped rows + packed weights
__device__ __forceinline__ void ymath(int oy, float s, float ty,
                                      int& y0, int& y1, u64& dy0, u64& dy1)
{
    const float yc = fmaf((float)oy, 2.0f / 511.0f, -1.0f);
    const float y  = 0.5f * (fmaf(s, yc, ty) + 1.0f) * (float)HH;
    y0 = (int)y;                 // trunc toward zero (matches astype(int32))
    y1 = y0 + 1;
    y0 = min(max(y0, 0), HH - 1);
    y1 = min(max(y1, 0), HH - 1);
    dy1 = pk2((float)y1 - y);
    dy0 = pk2(y - (float)y0);
}

__global__ void __launch_bounds__(256)
bilinear_pipe_kernel(const ulonglong2* __restrict__ X,
                     const float* __restrict__ scale,
                     const float* __restrict__ translate,
                     ulonglong2* __restrict__ out)
{
    const int t   = threadIdx.x;
    const int b   = blockIdx.z;            // uniform
    const int oy0 = blockIdx.y * ROWS;     // uniform

    const float s  = __ldg(&scale[b]);
    const float tx = __ldg(&translate[2 * b]);
    const float ty = __ldg(&translate[2 * b + 1]);

    // ---- per-thread x-side math (shared by all ROWS outputs) ----
    const int q  = t & 3;
    const int ox = (blockIdx.x << 6) + (t >> 2);
    const float xc = fmaf((float)ox, 2.0f / 511.0f, -1.0f);
    const float x  = 0.5f * (fmaf(s, xc, tx) + 1.0f) * (float)WW;
    int x0 = (int)x;
    int x1 = x0 + 1;
    x0 = min(max(x0, 0), WW - 1);
    x1 = min(max(x1, 0), WW - 1);
    const u64 dx1 = pk2((float)x1 - x);
    const u64 dx0 = pk2(x - (float)x0);

    const int c0 = (x0 << 2) + q;
    const int c1 = (x1 << 2) + q;

    const ulonglong2* __restrict__ Xb = X + b * (HH * WW * 4);
    ulonglong2* __restrict__ O = out + ((b * HH + oy0) << 11) + (blockIdx.x << 8) + t;

    // ---- prologue ----
    int y0r, y1r; u64 dy0r, dy1r;
    ymath(oy0, s, ty, y0r, y1r, dy0r, dy1r);
    int cury0 = y0r;

    // h0 for the first row; prefetch y1 rows for r=0 and r=1
    H2 h0 = hcombine(rawload(Xb + (y0r << 11), c0, c1), dx0, dx1);

    int y0n, y1n; u64 dy0n, dy1n;              // y info for r+1 (rolls forward)
    ymath(oy0 + 1, s, ty, y0n, y1n, dy0n, dy1n);

    P2 A = rawload(Xb + (y1r << 11), c0, c1);  // row y1(0)
    P2 Bv = rawload(Xb + (y1n << 11), c0, c1); // row y1(1)

    #pragma unroll
    for (int r = 0; r < ROWS; ++r) {
        // prefetch r+2's y-row (uniform address math only)
        P2 Cv;
        int y0f = 0, y1f = 0; u64 dy0f = 0, dy1f = 0;
        if (r + 2 < ROWS) {
            ymath(oy0 + r + 2, s, ty, y0f, y1f, dy0f, dy1f);
            Cv = rawload(Xb + (y1f << 11), c0, c1);
        }

        // consume stage A: h1 of current row (load issued 2 iterations ago)
        const H2 h1 = hcombine(A, dx0, dx1);

        // blend + streaming store
        ulonglong2 o;
        o.x = fma2(dy1r, h0.x, mul2(dy0r, h1.x));
        o.y = fma2(dy1r, h0.y, mul2(dy0r, h1.y));
        __stcs(O + (r << 11), o);

        // branch-free advance for next iteration (s<1 => step 0 or 1)
        if (r + 1 < ROWS) {
            const bool adv = (y0n != cury0);
            h0.x = adv ? h1.x : h0.x;
            h0.y = adv ? h1.y : h0.y;
            cury0 = y0n;
            // roll y info and pipeline stages
            y0r = y0n; y1r = y1n; dy0r = dy0n; dy1r = dy1n;
            y0n = y0f; y1n = y1f; dy0n = dy0f; dy1n = dy1f;
            A = Bv; Bv = Cv;
        }
    }
}

extern "C" void kernel_launch(void* const* d_in, const int* in_sizes, int n_in,
                              void* d_out, int out_size)
{
    const float* X         = (const float*)d_in[0];
    const float* scale     = (const float*)d_in[1];
    const float* translate = (const float*)d_in[2];

    dim3 grid(WW / 64, HH / ROWS, BB);   // (8, 32, 16) = 4096 blocks
    bilinear_pipe_kernel<<<grid, 256>>>((const ulonglong2*)X, scale, translate,
                                        (ulonglong2*)d_out);
}

// round 14
// speedup vs baseline: 1.0163x; 1.0039x over previous
#include <cuda_runtime.h>

// BilinearInterpolation: B=16, H=W=512, C=16 fp32.
// R14: TLP attack. Five ILP restructurings all pinned at ~50us with nothing
// saturated => not enough warps to cover L2-hit latency on row gathers.
// __launch_bounds__(256, 8) forces 2048 threads/SM (occ ~100%, regs<=32).
// ROWS=8 keeps the live set small enough for 32 regs. Branch-free select
// advance (R12), thread-per-quad, f32x2 packed math, __stcs stores.

#define BB 16
#define HH 512
#define WW 512
#define ROWS 8

typedef unsigned long long u64;

__device__ __forceinline__ u64 pk2(float v) {
    u64 r; asm("mov.b64 %0, {%1, %1};" : "=l"(r) : "f"(v)); return r;
}
__device__ __forceinline__ u64 mul2(u64 a, u64 b) {
    u64 r; asm("mul.rn.f32x2 %0, %1, %2;" : "=l"(r) : "l"(a), "l"(b)); return r;
}
__device__ __forceinline__ u64 fma2(u64 a, u64 b, u64 c) {
    u64 r; asm("fma.rn.f32x2 %0, %1, %2, %3;" : "=l"(r) : "l"(a), "l"(b), "l"(c)); return r;
}

struct H2 { u64 x, y; };   // horizontal interpolant of one input row (4 floats)

__device__ __forceinline__ H2 hload(const ulonglong2* __restrict__ row,
                                    int c0, int c1, u64 dx0, u64 dx1)
{
    const ulonglong2 p0 = __ldg(row + c0);
    const ulonglong2 p1 = __ldg(row + c1);
    H2 h;
    h.x = fma2(dx1, p0.x, mul2(dx0, p1.x));
    h.y = fma2(dx1, p0.y, mul2(dx0, p1.y));
    return h;
}

__global__ void __launch_bounds__(256, 8)
bilinear_occ_kernel(const ulonglong2* __restrict__ X,
                    const float* __restrict__ scale,
                    const float* __restrict__ translate,
                    ulonglong2* __restrict__ out)
{
    const int t   = threadIdx.x;
    const int b   = blockIdx.z;            // uniform
    const int oy0 = blockIdx.y * ROWS;     // uniform

    // ---- uniform batch params ----
    const float s  = __ldg(&scale[b]);
    const float tx = __ldg(&translate[2 * b]);
    const float ty = __ldg(&translate[2 * b + 1]);

    // ---- per-thread x-side math (shared by all ROWS outputs) ----
    const int q  = t & 3;
    const int ox = (blockIdx.x << 6) + (t >> 2);
    const float xc = fmaf((float)ox, 2.0f / 511.0f, -1.0f);
    const float x  = 0.5f * (fmaf(s, xc, tx) + 1.0f) * (float)WW;
    int x0 = (int)x;            // trunc toward zero (matches astype(int32))
    int x1 = x0 + 1;
    x0 = min(max(x0, 0), WW - 1);
    x1 = min(max(x1, 0), WW - 1);
    const u64 dx1 = pk2((float)x1 - x);
    const u64 dx0 = pk2(x - (float)x0);

    const int c0 = (x0 << 2) + q;
    const int c1 = (x1 << 2) + q;

    const ulonglong2* __restrict__ Xb = X + b * (HH * WW * 4);
    ulonglong2* __restrict__ O = out + ((b * HH + oy0) << 11) + (blockIdx.x << 8) + t;

    // ---- prologue: row 0 of this block ----
    float yc = fmaf((float)oy0, 2.0f / 511.0f, -1.0f);
    float y  = 0.5f * (fmaf(s, yc, ty) + 1.0f) * (float)HH;
    int y0 = (int)y;
    int y1 = y0 + 1;
    y0 = min(max(y0, 0), HH - 1);
    y1 = min(max(y1, 0), HH - 1);

    H2 h0 = hload(Xb + (y0 << 11), c0, c1, dx0, dx1);
    H2 h1 = hload(Xb + (y1 << 11), c0, c1, dx0, dx1);
    int cury0 = y0;

    {
        const u64 dy1 = pk2((float)y1 - y);
        const u64 dy0 = pk2(y - (float)y0);
        ulonglong2 o;
        o.x = fma2(dy1, h0.x, mul2(dy0, h1.x));
        o.y = fma2(dy1, h0.y, mul2(dy0, h1.y));
        __stcs(O, o);
    }

    // ---- branch-free main loop ----
    #pragma unroll
    for (int r = 1; r < ROWS; ++r) {
        yc = fmaf((float)(oy0 + r), 2.0f / 511.0f, -1.0f);
        y  = 0.5f * (fmaf(s, yc, ty) + 1.0f) * (float)HH;
        y0 = (int)y;
        y1 = y0 + 1;
        y0 = min(max(y0, 0), HH - 1);
        y1 = min(max(y1, 0), HH - 1);
        const u64 dy1 = pk2((float)y1 - y);
        const u64 dy0 = pk2(y - (float)y0);

        // register-select cache advance (s<1 => step 0 or 1; clamp-safe)
        const bool adv = (y0 != cury0);
        h0.x = adv ? h1.x : h0.x;
        h0.y = adv ? h1.y : h0.y;
        cury0 = y0;

        // unconditional reload of the high row (L1/L2 hit when unchanged)
        h1 = hload(Xb + (y1 << 11), c0, c1, dx0, dx1);

        ulonglong2 o;
        o.x = fma2(dy1, h0.x, mul2(dy0, h1.x));
        o.y = fma2(dy1, h0.y, mul2(dy0, h1.y));
        __stcs(O + (r << 11), o);
    }
}

extern "C" void kernel_launch(void* const* d_in, const int* in_sizes, int n_in,
                              void* d_out, int out_size)
{
    const float* X         = (const float*)d_in[0];
    const float* scale     = (const float*)d_in[1];
    const float* translate = (const float*)d_in[2];

    dim3 grid(WW / 64, HH / ROWS, BB);   // (8, 64, 16) = 8192 blocks
    bilinear_occ_kernel<<<grid, 256>>>((const ulonglong2*)X, scale, translate,
                                       (ulonglong2*)d_out);
}

// round 15
// speedup vs baseline: 1.0236x; 1.0072x over previous
#include <cuda_runtime.h>

// BilinearInterpolation: B=16, H=W=512, C=16 fp32.
// R15: instruction diet. The block-uniform y-side math (~10 instr/row,
// redundantly executed by all 256 threads in R14) is computed ONCE per block
// by threads 0..ROWS-1 into a tiny smem table; the per-row body shrinks to
// LDS.128 + 2 SEL + 2 LDG + 8 f32x2 + STG. Otherwise identical to R14:
// ROWS=8, launch_bounds(256,8), branch-free select advance, thread-per-quad,
// f32x2 packed math, __stcs streaming stores.

#define BB 16
#define HH 512
#define WW 512
#define ROWS 8

typedef unsigned long long u64;

__device__ __forceinline__ u64 pk2(float v) {
    u64 r; asm("mov.b64 %0, {%1, %1};" : "=l"(r) : "f"(v)); return r;
}
__device__ __forceinline__ u64 mul2(u64 a, u64 b) {
    u64 r; asm("mul.rn.f32x2 %0, %1, %2;" : "=l"(r) : "l"(a), "l"(b)); return r;
}
__device__ __forceinline__ u64 fma2(u64 a, u64 b, u64 c) {
    u64 r; asm("fma.rn.f32x2 %0, %1, %2, %3;" : "=l"(r) : "l"(a), "l"(b), "l"(c)); return r;
}

struct H2 { u64 x, y; };   // horizontal interpolant of one input row (4 floats)

__device__ __forceinline__ H2 hload(const ulonglong2* __restrict__ row,
                                    int c0, int c1, u64 dx0, u64 dx1)
{
    const ulonglong2 p0 = __ldg(row + c0);
    const ulonglong2 p1 = __ldg(row + c1);
    H2 h;
    h.x = fma2(dx1, p0.x, mul2(dx0, p1.x));
    h.y = fma2(dx1, p0.y, mul2(dx0, p1.y));
    return h;
}

__global__ void __launch_bounds__(256, 8)
bilinear_tab_kernel(const ulonglong2* __restrict__ X,
                    const float* __restrict__ scale,
                    const float* __restrict__ translate,
                    ulonglong2* __restrict__ out)
{
    __shared__ int4 ytab[ROWS];   // per row: {y0, y1*W*4, bits(dy0), bits(dy1)}

    const int t   = threadIdx.x;
    const int b   = blockIdx.z;            // uniform
    const int oy0 = blockIdx.y * ROWS;     // uniform

    // ---- uniform batch params ----
    const float s  = __ldg(&scale[b]);
    const float tx = __ldg(&translate[2 * b]);
    const float ty = __ldg(&translate[2 * b + 1]);

    // ---- y-table: threads 0..ROWS-1 compute one row each ----
    if (t < ROWS) {
        const float yc = fmaf((float)(oy0 + t), 2.0f / 511.0f, -1.0f);
        const float y  = 0.5f * (fmaf(s, yc, ty) + 1.0f) * (float)HH;
        int y0 = (int)y;            // trunc toward zero (matches astype(int32))
        int y1 = y0 + 1;
        y0 = min(max(y0, 0), HH - 1);
        y1 = min(max(y1, 0), HH - 1);
        ytab[t] = make_int4(y0, y1 << 11,
                            __float_as_int(y - (float)y0),
                            __float_as_int((float)y1 - y));
    }

    // ---- per-thread x-side math (shared by all ROWS outputs) ----
    const int q  = t & 3;
    const int ox = (blockIdx.x << 6) + (t >> 2);
    const float xc = fmaf((float)ox, 2.0f / 511.0f, -1.0f);
    const float x  = 0.5f * (fmaf(s, xc, tx) + 1.0f) * (float)WW;
    int x0 = (int)x;
    int x1 = x0 + 1;
    x0 = min(max(x0, 0), WW - 1);
    x1 = min(max(x1, 0), WW - 1);
    const u64 dx1 = pk2((float)x1 - x);
    const u64 dx0 = pk2(x - (float)x0);

    const int c0 = (x0 << 2) + q;
    const int c1 = (x1 << 2) + q;

    const ulonglong2* __restrict__ Xb = X + b * (HH * WW * 4);
    ulonglong2* __restrict__ O = out + ((b * HH + oy0) << 11) + (blockIdx.x << 8) + t;

    __syncthreads();

    // ---- prologue: row 0 ----
    int4 e = ytab[0];
    int cury0 = e.x;
    H2 h0 = hload(Xb + (e.x << 11), c0, c1, dx0, dx1);
    H2 h1 = hload(Xb + e.y,         c0, c1, dx0, dx1);
    {
        const u64 dy0 = pk2(__int_as_float(e.z));
        const u64 dy1 = pk2(__int_as_float(e.w));
        ulonglong2 o;
        o.x = fma2(dy1, h0.x, mul2(dy0, h1.x));
        o.y = fma2(dy1, h0.y, mul2(dy0, h1.y));
        __stcs(O, o);
    }

    // ---- branch-free main loop (per-row: LDS + SEL + 2 LDG + 8 f32x2 + STG) ----
    #pragma unroll
    for (int r = 1; r < ROWS; ++r) {
        e = ytab[r];

        // register-select cache advance (s<1 => step 0 or 1; clamp-safe)
        const bool adv = (e.x != cury0);
        h0.x = adv ? h1.x : h0.x;
        h0.y = adv ? h1.y : h0.y;
        cury0 = e.x;

        // unconditional reload of the high row (L1/L2 hit when unchanged)
        h1 = hload(Xb + e.y, c0, c1, dx0, dx1);

        const u64 dy0 = pk2(__int_as_float(e.z));
        const u64 dy1 = pk2(__int_as_float(e.w));
        ulonglong2 o;
        o.x = fma2(dy1, h0.x, mul2(dy0, h1.x));
        o.y = fma2(dy1, h0.y, mul2(dy0, h1.y));
        __stcs(O + (r << 11), o);
    }
}

extern "C" void kernel_launch(void* const* d_in, const int* in_sizes, int n_in,
                              void* d_out, int out_size)
{
    const float* X         = (const float*)d_in[0];
    const float* scale     = (const float*)d_in[1];
    const float* translate = (const float*)d_in[2];

    dim3 grid(WW / 64, HH / ROWS, BB);   // (8, 64, 16) = 8192 blocks
    bilinear_tab_kernel<<<grid, 256>>>((const ulonglong2*)X, scale, translate,
                                       (ulonglong2*)d_out);
}